// round 12
// baseline (speedup 1.0000x reference)
#include <cuda_runtime.h>
#include <cuda_bf16.h>
#include <cstdint>

#define T_STEPS 512
#define BATCH   64
#define INDIM   1024
#define HID     1024
#define G4      4096

// scan config
#define NBLK     128
#define SCAN_THR 512
// scan smem layout (bytes)
#define WSH_OFF  0
#define WSL_OFF  65536
#define HB_OFF   131072
#define RED_OFF  196608
#define SCAN_SMEM 204800   // 128K W hi/lo + 2 x 32K h chunks + 8K reduction

// xg mma config (R5, proven)
#define MM_BM   128
#define MM_BN   128
#define MM_KC   64
#define MM_THR  256

// ---------------------------------------------------------------------------
// Global scratch
// ---------------------------------------------------------------------------
__device__ float g_xg[(size_t)T_STEPS * BATCH * G4];   // [m][j'] permuted, bias included
__device__ __nv_bfloat16 g_hh[2][BATCH * HID];         // h hi, [b][hj], double buffered
__device__ __nv_bfloat16 g_hl[2][BATCH * HID];         // h lo
__device__ __nv_bfloat16 g_xh[(size_t)T_STEPS * BATCH * INDIM];
__device__ __nv_bfloat16 g_xl[(size_t)T_STEPS * BATCH * INDIM];
__device__ __nv_bfloat16 g_wh[(size_t)G4 * INDIM];     // W_ih permuted rows, bf16 hi
__device__ __nv_bfloat16 g_wl[(size_t)G4 * INDIM];     // W_ih bf16 lo
__device__ __nv_bfloat16 g_uh[(size_t)G4 * HID];       // W_hh permuted rows, bf16 hi
__device__ __nv_bfloat16 g_ul[(size_t)G4 * HID];       // W_hh bf16 lo
__device__ float g_bias[G4];
__device__ unsigned int g_flag[8];     // monotonic per-group publication counters

// ---------------------------------------------------------------------------
// Ampere-ISA helpers (plain compute_103)
// ---------------------------------------------------------------------------
__device__ __forceinline__ uint32_t smem_to_u32(const void* p) {
    uint32_t a;
    asm("{ .reg .u64 t; cvta.to.shared.u64 t, %1; cvt.u32.u64 %0, t; }" : "=r"(a) : "l"(p));
    return a;
}
__device__ __forceinline__ void ldmx4(uint32_t& r0, uint32_t& r1, uint32_t& r2,
                                      uint32_t& r3, uint32_t a) {
    asm volatile("ldmatrix.sync.aligned.m8n8.x4.shared.b16 {%0,%1,%2,%3}, [%4];"
                 : "=r"(r0), "=r"(r1), "=r"(r2), "=r"(r3) : "r"(a));
}
__device__ __forceinline__ void mma16816(float* d, const uint32_t* a, const uint32_t* b) {
    asm volatile(
        "mma.sync.aligned.m16n8k16.row.col.f32.bf16.bf16.f32 "
        "{%0,%1,%2,%3},{%4,%5,%6,%7},{%8,%9},{%0,%1,%2,%3};"
        : "+f"(d[0]), "+f"(d[1]), "+f"(d[2]), "+f"(d[3])
        : "r"(a[0]), "r"(a[1]), "r"(a[2]), "r"(a[3]), "r"(b[0]), "r"(b[1]));
}
#define CP_ASYNC16(s, g) \
    asm volatile("cp.async.cg.shared.global [%0], [%1], 16;" :: "r"(s), "l"(g) : "memory")
#define CP_COMMIT()  asm volatile("cp.async.commit_group;" ::: "memory")
#define CP_WAIT0()   asm volatile("cp.async.wait_group 0;" ::: "memory")
#define BAR_SYNC(id, n) \
    asm volatile("bar.sync %0, %1;" :: "r"(id), "r"(n) : "memory")

__device__ __forceinline__ unsigned ld_acq(const unsigned* p) {
    unsigned v;
    asm volatile("ld.acquire.gpu.global.u32 %0, [%1];" : "=r"(v) : "l"(p) : "memory");
    return v;
}
__device__ __forceinline__ void red_release_add1(unsigned* p) {
    asm volatile("red.release.gpu.global.add.u32 [%0], 1;" :: "l"(p) : "memory");
}
// single-thread poll: all 8 group counters >= tgt
__device__ __forceinline__ void poll_all_flags(unsigned tgt) {
    for (;;) {
        bool ok = true;
#pragma unroll
        for (int g = 0; g < 8; g++) ok &= (ld_acq(&g_flag[g]) >= tgt);
        if (ok) return;
        __nanosleep(32);
    }
}

__device__ __forceinline__ float sigf(float x) {
    return __fdividef(1.0f, 1.0f + __expf(-x));
}
__device__ __forceinline__ float tanh_fast(float x) {
    return __fdividef(2.0f, 1.0f + __expf(-2.0f * x)) - 1.0f;
}

// ---------------------------------------------------------------------------
// Conversion: bf16 hi/lo of x, permuted W_ih AND permuted W_hh; bias; resets
// ---------------------------------------------------------------------------
#define CV_XU 8388608u
#define CV_WU 1048576u
#define CV_UU 1048576u
#define CV_BU 1024u
#define CV_HU 16384u
#define CV_GRID 41028u

__global__ void convert_inputs(const float* __restrict__ x,
                               const float* __restrict__ Wih,
                               const float* __restrict__ Whh,
                               const float* __restrict__ bih,
                               const float* __restrict__ bhh) {
    unsigned u = blockIdx.x * 256u + threadIdx.x;
    if (u < CV_XU) {
        float4 v = __ldg((const float4*)x + u);
        __nv_bfloat162 h01 = __floats2bfloat162_rn(v.x, v.y);
        __nv_bfloat162 h23 = __floats2bfloat162_rn(v.z, v.w);
        __nv_bfloat162 l01 = __floats2bfloat162_rn(v.x - __bfloat162float(h01.x),
                                                   v.y - __bfloat162float(h01.y));
        __nv_bfloat162 l23 = __floats2bfloat162_rn(v.z - __bfloat162float(h23.x),
                                                   v.w - __bfloat162float(h23.y));
        *(__nv_bfloat162*)(g_xh + (size_t)u * 4)     = h01;
        *(__nv_bfloat162*)(g_xh + (size_t)u * 4 + 2) = h23;
        *(__nv_bfloat162*)(g_xl + (size_t)u * 4)     = l01;
        *(__nv_bfloat162*)(g_xl + (size_t)u * 4 + 2) = l23;
    } else if (u < CV_XU + CV_WU) {
        unsigned uw = u - CV_XU;
        int np = uw >> 8;
        int kq = uw & 255;
        int jo = (np & 3) * HID + (np >> 2);
        float4 v = __ldg((const float4*)(Wih + (size_t)jo * INDIM) + kq);
        __nv_bfloat162 h01 = __floats2bfloat162_rn(v.x, v.y);
        __nv_bfloat162 h23 = __floats2bfloat162_rn(v.z, v.w);
        __nv_bfloat162 l01 = __floats2bfloat162_rn(v.x - __bfloat162float(h01.x),
                                                   v.y - __bfloat162float(h01.y));
        __nv_bfloat162 l23 = __floats2bfloat162_rn(v.z - __bfloat162float(h23.x),
                                                   v.w - __bfloat162float(h23.y));
        size_t base = (size_t)np * INDIM + kq * 4;
        *(__nv_bfloat162*)(g_wh + base)     = h01;
        *(__nv_bfloat162*)(g_wh + base + 2) = h23;
        *(__nv_bfloat162*)(g_wl + base)     = l01;
        *(__nv_bfloat162*)(g_wl + base + 2) = l23;
    } else if (u < CV_XU + CV_WU + CV_UU) {
        unsigned uw = u - CV_XU - CV_WU;
        int np = uw >> 8;
        int kq = uw & 255;
        int jo = (np & 3) * HID + (np >> 2);
        float4 v = __ldg((const float4*)(Whh + (size_t)jo * HID) + kq);
        __nv_bfloat162 h01 = __floats2bfloat162_rn(v.x, v.y);
        __nv_bfloat162 h23 = __floats2bfloat162_rn(v.z, v.w);
        __nv_bfloat162 l01 = __floats2bfloat162_rn(v.x - __bfloat162float(h01.x),
                                                   v.y - __bfloat162float(h01.y));
        __nv_bfloat162 l23 = __floats2bfloat162_rn(v.z - __bfloat162float(h23.x),
                                                   v.w - __bfloat162float(h23.y));
        size_t base = (size_t)np * HID + kq * 4;
        *(__nv_bfloat162*)(g_uh + base)     = h01;
        *(__nv_bfloat162*)(g_uh + base + 2) = h23;
        *(__nv_bfloat162*)(g_ul + base)     = l01;
        *(__nv_bfloat162*)(g_ul + base + 2) = l23;
    } else if (u < CV_XU + CV_WU + CV_UU + CV_BU) {
        unsigned ub = u - CV_XU - CV_WU - CV_UU;
        if (ub == 0) {
#pragma unroll
            for (int g = 0; g < 8; g++) g_flag[g] = 0u;
        }
#pragma unroll
        for (int c = 0; c < 4; c++) {
            int np = ub * 4 + c;
            int jo = (np & 3) * HID + (np >> 2);
            g_bias[np] = bih[jo] + bhh[jo];
        }
    } else if (u < CV_XU + CV_WU + CV_UU + CV_BU + CV_HU) {
        unsigned uh = u - CV_XU - CV_WU - CV_UU - CV_BU;   // 0..16383
        if (uh < 8192u)
            reinterpret_cast<uint4*>(&g_hh[0][0])[uh] = make_uint4(0, 0, 0, 0);
        else
            reinterpret_cast<uint4*>(&g_hl[0][0])[uh - 8192u] = make_uint4(0, 0, 0, 0);
    }
}

// ---------------------------------------------------------------------------
// xg via mma.sync bf16 (3-term split) — R5, proven (unchanged)
// ---------------------------------------------------------------------------
#define XR_AH 0
#define XR_AL 16384
#define XR_BH 32768
#define XR_BL 49152
#define XR_BUF 65536
#define XS_TOTAL (2 * XR_BUF)

__global__ __launch_bounds__(MM_THR, 1) void xg_mma() {
    extern __shared__ char smem[];
    const uint32_t sb = smem_to_u32(smem);
    const int tid = threadIdx.x;
    const int lid = tid & 31;
    const int wid = tid >> 5;
    const int wm  = wid & 3;
    const int wn  = wid >> 2;
    const int n0  = blockIdx.x * MM_BN;
    const int m0  = blockIdx.y * MM_BM;

    const int s_row = tid >> 3;
    const int s_c16 = tid & 7;
    const int a_ml = lid & 15;
    const int a_kh = (lid >> 4) & 1;
    const int b_nl = (lid & 7) + ((lid & 16) ? 8 : 0);
    const int b_kh = (lid >> 3) & 1;

    float acc[2][8][4];
#pragma unroll
    for (int i = 0; i < 2; i++)
#pragma unroll
        for (int j = 0; j < 8; j++)
#pragma unroll
            for (int q = 0; q < 4; q++) acc[i][j][q] = 0.f;

    auto stage = [&](int c, int buf) {
        const int kb = c * MM_KC;
        const uint32_t base = sb + buf * XR_BUF;
#pragma unroll
        for (int p = 0; p < 4; p++) {
            int row = s_row + p * 32;
            uint32_t so = (uint32_t)(row * 128 + ((s_c16 ^ (row & 7)) * 16));
            const __nv_bfloat16* ah = g_xh + (size_t)(m0 + row) * INDIM + kb + s_c16 * 8;
            const __nv_bfloat16* al = g_xl + (size_t)(m0 + row) * INDIM + kb + s_c16 * 8;
            const __nv_bfloat16* bh = g_wh + (size_t)(n0 + row) * INDIM + kb + s_c16 * 8;
            const __nv_bfloat16* bl = g_wl + (size_t)(n0 + row) * INDIM + kb + s_c16 * 8;
            CP_ASYNC16(base + XR_AH + so, ah);
            CP_ASYNC16(base + XR_AL + so, al);
            CP_ASYNC16(base + XR_BH + so, bh);
            CP_ASYNC16(base + XR_BL + so, bl);
        }
        CP_COMMIT();
    };

    stage(0, 0);

#pragma unroll 1
    for (int c = 0; c < 16; c++) {
        CP_WAIT0();
        __syncthreads();
        if (c < 15) stage(c + 1, (c + 1) & 1);

        const uint32_t base = sb + (c & 1) * XR_BUF;
#pragma unroll
        for (int kk = 0; kk < 4; kk++) {
            uint32_t ahf[2][4], alf[2][4];
#pragma unroll
            for (int mf = 0; mf < 2; mf++) {
                int r = wm * 32 + mf * 16 + a_ml;
                uint32_t co = (uint32_t)((((kk * 2 + a_kh) ^ (r & 7)) * 16) + r * 128);
                ldmx4(ahf[mf][0], ahf[mf][1], ahf[mf][2], ahf[mf][3], base + XR_AH + co);
                ldmx4(alf[mf][0], alf[mf][1], alf[mf][2], alf[mf][3], base + XR_AL + co);
            }
#pragma unroll
            for (int np = 0; np < 4; np++) {
                int r = wn * 64 + np * 16 + b_nl;
                uint32_t co = (uint32_t)((((kk * 2 + b_kh) ^ (r & 7)) * 16) + r * 128);
                uint32_t bh[4], bl[4];
                ldmx4(bh[0], bh[1], bh[2], bh[3], base + XR_BH + co);
                ldmx4(bl[0], bl[1], bl[2], bl[3], base + XR_BL + co);
#pragma unroll
                for (int mf = 0; mf < 2; mf++) {
                    mma16816(acc[mf][np * 2 + 0], ahf[mf], &bh[0]);
                    mma16816(acc[mf][np * 2 + 1], ahf[mf], &bh[2]);
                    mma16816(acc[mf][np * 2 + 0], ahf[mf], &bl[0]);
                    mma16816(acc[mf][np * 2 + 1], ahf[mf], &bl[2]);
                    mma16816(acc[mf][np * 2 + 0], alf[mf], &bh[0]);
                    mma16816(acc[mf][np * 2 + 1], alf[mf], &bh[2]);
                }
            }
        }
        __syncthreads();
    }

    const int lr = lid >> 2;
    const int lc = (lid & 3) * 2;
#pragma unroll
    for (int mf = 0; mf < 2; mf++) {
#pragma unroll
        for (int nf = 0; nf < 8; nf++) {
            int m = m0 + wm * 32 + mf * 16 + lr;
            int n = n0 + wn * 64 + nf * 8 + lc;
            float2 bv = __ldg((const float2*)(g_bias + n));
            float2 o0 = make_float2(acc[mf][nf][0] + bv.x, acc[mf][nf][1] + bv.y);
            float2 o1 = make_float2(acc[mf][nf][2] + bv.x, acc[mf][nf][3] + bv.y);
            *reinterpret_cast<float2*>(g_xg + (size_t)m * G4 + n)       = o0;
            *reinterpret_cast<float2*>(g_xg + (size_t)(m + 8) * G4 + n) = o1;
        }
    }
}

// ---------------------------------------------------------------------------
// Tensorized persistent LSTM scan: 16 warps, wm4 (m16) x wn2 (n16) x ks2 (k512).
//   Step sync = published-counter poll (1 thread/block) instead of rendezvous
//   barrier; symmetric epilogue: warp (wm,wn,ks) owns output rows rr==ks.
// ---------------------------------------------------------------------------
__global__ __launch_bounds__(SCAN_THR, 1) void lstm_scan(float* __restrict__ out) {
    extern __shared__ char smem[];
    const uint32_t sb = smem_to_u32(smem);
    const int tid = threadIdx.x;
    const int lid = tid & 31;
    const int wid = tid >> 5;          // 0..15
    const int wm  = wid & 3;           // m16 group (batch rows wm*16..+15)
    const int wn  = (wid >> 2) & 1;    // n16 group
    const int ks  = wid >> 3;          // k512 half; also owned row-half rr
    const int hbar = 1 + ks;           // named barrier id for this half
    const int jt  = blockIdx.x;
    const int j0  = jt * 32;
    const int my_group = (jt >> 3) & 7;

    const int a_ml = lid & 15;
    const int a_kh = (lid >> 4) & 1;
    const int b_nl = (lid & 7) + ((lid & 16) ? 8 : 0);
    const int b_kh = (lid >> 3) & 1;
    const int lc   = (lid & 3) * 2;
    const int lr   = lid >> 2;
    const int pa   = a_ml & 7;
    const int pb   = b_nl & 7;

    // --- persistent W_hh slice preload: [32 cols][2048 B] hi/lo, swizzled ---
#pragma unroll 4
    for (int i = 0; i < 8; i++) {
        int g = tid + 512 * i;            // 0..4095
        int row = g >> 7;                 // 0..31
        int slot = g & 127;
        uint4 vh = *(const uint4*)(g_uh + (size_t)(j0 + row) * HID + slot * 8);
        uint4 vl = *(const uint4*)(g_ul + (size_t)(j0 + row) * HID + slot * 8);
        uint32_t doff = (uint32_t)(row * 2048 + (slot >> 3) * 128 +
                                   (((slot & 7) ^ (row & 7)) * 16));
        *(uint4*)(smem + WSH_OFF + doff) = vh;
        *(uint4*)(smem + WSL_OFF + doff) = vl;
    }
    __syncthreads();

    // h chunk staging: task = (row b, k-half); 4 threads per task, 2 slots each.
    const int st_task = tid >> 2;        // 0..127
    const int st_b = st_task & 63;
    const int st_h = st_task >> 6;       // k-half (== ks for every thread)
    const int st_s = (tid & 3) * 2;

    // fragment bases
    const int a_row = wm * 16 + a_ml;
    const int b_row = wn * 16 + b_nl;
    const uint32_t bhb = sb + WSH_OFF + (uint32_t)(b_row * 2048);
    const uint32_t blb = sb + WSL_OFF + (uint32_t)(b_row * 2048);

    // epilogue geometry: this warp owns batch row b_own (+ its hj cols)
    const int b_own = wm * 16 + lr + ks * 8;
    const int tile  = wm * 2 + wn;       // 0..7

    float c_[2] = {0.f, 0.f};

#pragma unroll 1
    for (int t = 0; t < T_STEPS; t++) {
        const int cur = t & 1, nxt = cur ^ 1;
        const __nv_bfloat16* hhs = g_hh[cur];
        const __nv_bfloat16* hls = g_hl[cur];

        // step-start publication poll (single thread, then CTA release)
        if (t != 0) {
            if (tid == 0) poll_all_flags(16u * (unsigned)t);
            __syncthreads();
        }

        // xg prefetch for the rows this warp owns (hidden under k-loop)
        float2 xv[2];
#pragma unroll
        for (int nt = 0; nt < 2; nt++) {
            int col = j0 + wn * 16 + nt * 8 + lc;
            xv[nt] = *(const float2*)(g_xg + (size_t)t * (BATCH * G4) +
                                      (size_t)b_own * G4 + col);
        }

        float acc[2][4];
#pragma unroll
        for (int nt = 0; nt < 2; nt++)
#pragma unroll
            for (int q = 0; q < 4; q++) acc[nt][q] = 0.f;

        // stage chunk 0: (64 rows x 64k) for this half, hi+lo
        {
            const __nv_bfloat16* sH = hhs + st_b * HID + st_h * 512;
            const __nv_bfloat16* sL = hls + st_b * HID + st_h * 512;
            uint32_t dst = sb + HB_OFF + (uint32_t)(st_h * 16384 + st_b * 128);
#pragma unroll
            for (int j = 0; j < 2; j++) {
                int s = st_s + j;
                uint32_t doff = (uint32_t)((s ^ (st_b & 7)) * 16);
                CP_ASYNC16(dst + doff,        sH + s * 8);
                CP_ASYNC16(dst + 8192 + doff, sL + s * 8);
            }
            CP_COMMIT();
        }

        int buf = 0;
#pragma unroll 1
        for (int c = 0; c < 8; c++) {
            CP_WAIT0();
            BAR_SYNC(hbar, 256);        // per-half: staging visible to this half
            if (c < 7) {
                const __nv_bfloat16* sH = hhs + st_b * HID + st_h * 512 + (c + 1) * 64;
                const __nv_bfloat16* sL = hls + st_b * HID + st_h * 512 + (c + 1) * 64;
                uint32_t dst = sb + HB_OFF +
                               (uint32_t)((buf ^ 1) * 32768 + st_h * 16384 + st_b * 128);
#pragma unroll
                for (int j = 0; j < 2; j++) {
                    int s = st_s + j;
                    uint32_t doff = (uint32_t)((s ^ (st_b & 7)) * 16);
                    CP_ASYNC16(dst + doff,        sH + s * 8);
                    CP_ASYNC16(dst + 8192 + doff, sL + s * 8);
                }
                CP_COMMIT();
            }

            const uint32_t hbase = sb + HB_OFF + (uint32_t)(buf * 32768 + ks * 16384);
#pragma unroll
            for (int kk = 0; kk < 4; kk++) {
                uint32_t aoff = (uint32_t)(a_row * 128 + (((kk * 2 + a_kh) ^ pa) * 16));
                uint32_t ahf[4], alf[4];
                ldmx4(ahf[0], ahf[1], ahf[2], ahf[3], hbase + aoff);
                ldmx4(alf[0], alf[1], alf[2], alf[3], hbase + 8192 + aoff);
                int slot = ks * 64 + c * 8 + kk * 2 + b_kh;
                uint32_t boff = (uint32_t)((slot >> 3) * 128 + (((slot & 7) ^ pb) * 16));
                uint32_t bh[4], bl[4];
                ldmx4(bh[0], bh[1], bh[2], bh[3], bhb + boff);
                ldmx4(bl[0], bl[1], bl[2], bl[3], blb + boff);
                mma16816(acc[0], ahf, &bh[0]);
                mma16816(acc[1], ahf, &bh[2]);
                mma16816(acc[0], ahf, &bl[0]);
                mma16816(acc[1], ahf, &bl[2]);
                mma16816(acc[0], alf, &bh[0]);
                mma16816(acc[1], alf, &bh[2]);
            }
            buf ^= 1;
        }

        // ---- symmetric split-K exchange: send non-owned row-half, recv own ----
        {
            char* wrp = smem + RED_OFF + (tile * 2 + (1 - ks)) * 512 + lid * 16;
            *reinterpret_cast<float4*>(wrp) =
                make_float4(acc[0][(1 - ks) * 2], acc[0][(1 - ks) * 2 + 1],
                            acc[1][(1 - ks) * 2], acc[1][(1 - ks) * 2 + 1]);
        }
        __syncthreads();
        float gsum[2][2];
        {
            const char* rrp = smem + RED_OFF + (tile * 2 + ks) * 512 + lid * 16;
            float4 r = *reinterpret_cast<const float4*>(rrp);
            gsum[0][0] = acc[0][ks * 2]     + r.x;
            gsum[0][1] = acc[0][ks * 2 + 1] + r.y;
            gsum[1][0] = acc[1][ks * 2]     + r.z;
            gsum[1][1] = acc[1][ks * 2 + 1] + r.w;
        }

        // gates for owned rows: even lanes (i,f), odd lanes (g,o); shfl pair
#pragma unroll
        for (int nt = 0; nt < 2; nt++) {
            float g0 = gsum[nt][0] + xv[nt].x;
            float g1 = gsum[nt][1] + xv[nt].y;
            float p0 = __shfl_xor_sync(0xffffffffu, g0, 1);
            float p1 = __shfl_xor_sync(0xffffffffu, g1, 1);
            float gi = sigf(g0);
            float gf = sigf(g1);
            float gg = tanh_fast(p0);
            float go = sigf(p1);
            float cc2 = gf * c_[nt] + gi * gg;
            c_[nt] = cc2;
            float v = go * tanh_fast(cc2);
            if ((lid & 1) == 0) {
                int hjg = jt * 8 + wn * 4 + nt * 2 + (lc >> 2);
                __nv_bfloat16 hi = __float2bfloat16(v);
                __nv_bfloat16 lo = __float2bfloat16(v - __bfloat162float(hi));
                g_hh[nxt][b_own * HID + hjg] = hi;
                g_hl[nxt][b_own * HID + hjg] = lo;
                if (t == T_STEPS - 1) out[b_own * HID + hjg] = v;
            }
        }

        // ---- publish h(t+1) for this block's group ----
        if (t != T_STEPS - 1) {
            __threadfence();
            __syncthreads();
            if (tid == 0) red_release_add1(&g_flag[my_group]);
        }
    }
}

// ---------------------------------------------------------------------------
extern "C" void kernel_launch(void* const* d_in, const int* in_sizes, int n_in,
                              void* d_out, int out_size) {
    const float* x   = (const float*)d_in[0];
    const float* Wih = (const float*)d_in[1];
    const float* Whh = (const float*)d_in[2];
    const float* bih = (const float*)d_in[3];
    const float* bhh = (const float*)d_in[4];
    float* out = (float*)d_out;

    cudaFuncSetAttribute(xg_mma, cudaFuncAttributeMaxDynamicSharedMemorySize, XS_TOTAL);
    cudaFuncSetAttribute(lstm_scan, cudaFuncAttributeMaxDynamicSharedMemorySize, SCAN_SMEM);

    convert_inputs<<<CV_GRID, 256>>>(x, Wih, Whh, bih, bhh);
    xg_mma<<<dim3(G4 / MM_BN, (T_STEPS * BATCH) / MM_BM), MM_THR, XS_TOTAL>>>();
    lstm_scan<<<NBLK, SCAN_THR, SCAN_SMEM>>>(out);
}

// round 13
// speedup vs baseline: 1.0719x; 1.0719x over previous
#include <cuda_runtime.h>
#include <cuda_bf16.h>
#include <cstdint>

#define T_STEPS 512
#define BATCH   64
#define INDIM   1024
#define HID     1024
#define G4      4096

// scan config
#define NBLK     128
#define SCAN_THR 512
// scan smem layout (bytes)
#define WSH_OFF  0
#define WSL_OFF  65536
#define HB_OFF   131072
#define RED_OFF  196608
#define SCAN_SMEM 204800   // 128K W hi/lo + 2 x 32K h chunks + 8K reduction

// xg mma config (R5, proven)
#define MM_BM   128
#define MM_BN   128
#define MM_KC   64
#define MM_THR  256

// ---------------------------------------------------------------------------
// Global scratch
// ---------------------------------------------------------------------------
__device__ float g_xg[(size_t)T_STEPS * BATCH * G4];   // [m][j'] permuted, bias included
__device__ __nv_bfloat16 g_hh[2][BATCH * HID];         // h hi, [b][hj], double buffered
__device__ __nv_bfloat16 g_hl[2][BATCH * HID];         // h lo
__device__ __nv_bfloat16 g_xh[(size_t)T_STEPS * BATCH * INDIM];
__device__ __nv_bfloat16 g_xl[(size_t)T_STEPS * BATCH * INDIM];
__device__ __nv_bfloat16 g_wh[(size_t)G4 * INDIM];     // W_ih permuted rows, bf16 hi
__device__ __nv_bfloat16 g_wl[(size_t)G4 * INDIM];     // W_ih bf16 lo
__device__ __nv_bfloat16 g_uh[(size_t)G4 * HID];       // W_hh permuted rows, bf16 hi
__device__ __nv_bfloat16 g_ul[(size_t)G4 * HID];       // W_hh bf16 lo
__device__ float g_bias[G4];
__device__ unsigned int g_count;
__device__ unsigned int g_sense;

// ---------------------------------------------------------------------------
// Ampere-ISA helpers (plain compute_103)
// ---------------------------------------------------------------------------
__device__ __forceinline__ uint32_t smem_to_u32(const void* p) {
    uint32_t a;
    asm("{ .reg .u64 t; cvta.to.shared.u64 t, %1; cvt.u32.u64 %0, t; }" : "=r"(a) : "l"(p));
    return a;
}
__device__ __forceinline__ void ldmx4(uint32_t& r0, uint32_t& r1, uint32_t& r2,
                                      uint32_t& r3, uint32_t a) {
    asm volatile("ldmatrix.sync.aligned.m8n8.x4.shared.b16 {%0,%1,%2,%3}, [%4];"
                 : "=r"(r0), "=r"(r1), "=r"(r2), "=r"(r3) : "r"(a));
}
__device__ __forceinline__ void mma16816(float* d, const uint32_t* a, const uint32_t* b) {
    asm volatile(
        "mma.sync.aligned.m16n8k16.row.col.f32.bf16.bf16.f32 "
        "{%0,%1,%2,%3},{%4,%5,%6,%7},{%8,%9},{%0,%1,%2,%3};"
        : "+f"(d[0]), "+f"(d[1]), "+f"(d[2]), "+f"(d[3])
        : "r"(a[0]), "r"(a[1]), "r"(a[2]), "r"(a[3]), "r"(b[0]), "r"(b[1]));
}
#define CP_ASYNC16(s, g) \
    asm volatile("cp.async.cg.shared.global [%0], [%1], 16;" :: "r"(s), "l"(g) : "memory")
#define CP_COMMIT()  asm volatile("cp.async.commit_group;" ::: "memory")
#define CP_WAIT0()   asm volatile("cp.async.wait_group 0;" ::: "memory")
#define BAR_SYNC(id, n) \
    asm volatile("bar.sync %0, %1;" :: "r"(id), "r"(n) : "memory")

__device__ __forceinline__ float sigf(float x) {
    return __fdividef(1.0f, 1.0f + __expf(-x));
}
__device__ __forceinline__ float tanh_fast(float x) {
    return __fdividef(2.0f, 1.0f + __expf(-2.0f * x)) - 1.0f;
}

// ---------------------------------------------------------------------------
// Conversion: bf16 hi/lo of x, permuted W_ih AND permuted W_hh; bias; resets
// ---------------------------------------------------------------------------
#define CV_XU 8388608u
#define CV_WU 1048576u
#define CV_UU 1048576u
#define CV_BU 1024u
#define CV_HU 16384u
#define CV_GRID 41028u

__global__ void convert_inputs(const float* __restrict__ x,
                               const float* __restrict__ Wih,
                               const float* __restrict__ Whh,
                               const float* __restrict__ bih,
                               const float* __restrict__ bhh) {
    unsigned u = blockIdx.x * 256u + threadIdx.x;
    if (u < CV_XU) {
        float4 v = __ldg((const float4*)x + u);
        __nv_bfloat162 h01 = __floats2bfloat162_rn(v.x, v.y);
        __nv_bfloat162 h23 = __floats2bfloat162_rn(v.z, v.w);
        __nv_bfloat162 l01 = __floats2bfloat162_rn(v.x - __bfloat162float(h01.x),
                                                   v.y - __bfloat162float(h01.y));
        __nv_bfloat162 l23 = __floats2bfloat162_rn(v.z - __bfloat162float(h23.x),
                                                   v.w - __bfloat162float(h23.y));
        *(__nv_bfloat162*)(g_xh + (size_t)u * 4)     = h01;
        *(__nv_bfloat162*)(g_xh + (size_t)u * 4 + 2) = h23;
        *(__nv_bfloat162*)(g_xl + (size_t)u * 4)     = l01;
        *(__nv_bfloat162*)(g_xl + (size_t)u * 4 + 2) = l23;
    } else if (u < CV_XU + CV_WU) {
        unsigned uw = u - CV_XU;
        int np = uw >> 8;
        int kq = uw & 255;
        int jo = (np & 3) * HID + (np >> 2);
        float4 v = __ldg((const float4*)(Wih + (size_t)jo * INDIM) + kq);
        __nv_bfloat162 h01 = __floats2bfloat162_rn(v.x, v.y);
        __nv_bfloat162 h23 = __floats2bfloat162_rn(v.z, v.w);
        __nv_bfloat162 l01 = __floats2bfloat162_rn(v.x - __bfloat162float(h01.x),
                                                   v.y - __bfloat162float(h01.y));
        __nv_bfloat162 l23 = __floats2bfloat162_rn(v.z - __bfloat162float(h23.x),
                                                   v.w - __bfloat162float(h23.y));
        size_t base = (size_t)np * INDIM + kq * 4;
        *(__nv_bfloat162*)(g_wh + base)     = h01;
        *(__nv_bfloat162*)(g_wh + base + 2) = h23;
        *(__nv_bfloat162*)(g_wl + base)     = l01;
        *(__nv_bfloat162*)(g_wl + base + 2) = l23;
    } else if (u < CV_XU + CV_WU + CV_UU) {
        unsigned uw = u - CV_XU - CV_WU;
        int np = uw >> 8;
        int kq = uw & 255;
        int jo = (np & 3) * HID + (np >> 2);
        float4 v = __ldg((const float4*)(Whh + (size_t)jo * HID) + kq);
        __nv_bfloat162 h01 = __floats2bfloat162_rn(v.x, v.y);
        __nv_bfloat162 h23 = __floats2bfloat162_rn(v.z, v.w);
        __nv_bfloat162 l01 = __floats2bfloat162_rn(v.x - __bfloat162float(h01.x),
                                                   v.y - __bfloat162float(h01.y));
        __nv_bfloat162 l23 = __floats2bfloat162_rn(v.z - __bfloat162float(h23.x),
                                                   v.w - __bfloat162float(h23.y));
        size_t base = (size_t)np * HID + kq * 4;
        *(__nv_bfloat162*)(g_uh + base)     = h01;
        *(__nv_bfloat162*)(g_uh + base + 2) = h23;
        *(__nv_bfloat162*)(g_ul + base)     = l01;
        *(__nv_bfloat162*)(g_ul + base + 2) = l23;
    } else if (u < CV_XU + CV_WU + CV_UU + CV_BU) {
        unsigned ub = u - CV_XU - CV_WU - CV_UU;
        if (ub == 0) { g_count = 0u; g_sense = 0u; }
#pragma unroll
        for (int c = 0; c < 4; c++) {
            int np = ub * 4 + c;
            int jo = (np & 3) * HID + (np >> 2);
            g_bias[np] = bih[jo] + bhh[jo];
        }
    } else if (u < CV_XU + CV_WU + CV_UU + CV_BU + CV_HU) {
        unsigned uh = u - CV_XU - CV_WU - CV_UU - CV_BU;   // 0..16383
        if (uh < 8192u)
            reinterpret_cast<uint4*>(&g_hh[0][0])[uh] = make_uint4(0, 0, 0, 0);
        else
            reinterpret_cast<uint4*>(&g_hl[0][0])[uh - 8192u] = make_uint4(0, 0, 0, 0);
    }
}

// ---------------------------------------------------------------------------
// xg via mma.sync bf16 (3-term split) — R5, proven (unchanged)
// ---------------------------------------------------------------------------
#define XR_AH 0
#define XR_AL 16384
#define XR_BH 32768
#define XR_BL 49152
#define XR_BUF 65536
#define XS_TOTAL (2 * XR_BUF)

__global__ __launch_bounds__(MM_THR, 1) void xg_mma() {
    extern __shared__ char smem[];
    const uint32_t sb = smem_to_u32(smem);
    const int tid = threadIdx.x;
    const int lid = tid & 31;
    const int wid = tid >> 5;
    const int wm  = wid & 3;
    const int wn  = wid >> 2;
    const int n0  = blockIdx.x * MM_BN;
    const int m0  = blockIdx.y * MM_BM;

    const int s_row = tid >> 3;
    const int s_c16 = tid & 7;
    const int a_ml = lid & 15;
    const int a_kh = (lid >> 4) & 1;
    const int b_nl = (lid & 7) + ((lid & 16) ? 8 : 0);
    const int b_kh = (lid >> 3) & 1;

    float acc[2][8][4];
#pragma unroll
    for (int i = 0; i < 2; i++)
#pragma unroll
        for (int j = 0; j < 8; j++)
#pragma unroll
            for (int q = 0; q < 4; q++) acc[i][j][q] = 0.f;

    auto stage = [&](int c, int buf) {
        const int kb = c * MM_KC;
        const uint32_t base = sb + buf * XR_BUF;
#pragma unroll
        for (int p = 0; p < 4; p++) {
            int row = s_row + p * 32;
            uint32_t so = (uint32_t)(row * 128 + ((s_c16 ^ (row & 7)) * 16));
            const __nv_bfloat16* ah = g_xh + (size_t)(m0 + row) * INDIM + kb + s_c16 * 8;
            const __nv_bfloat16* al = g_xl + (size_t)(m0 + row) * INDIM + kb + s_c16 * 8;
            const __nv_bfloat16* bh = g_wh + (size_t)(n0 + row) * INDIM + kb + s_c16 * 8;
            const __nv_bfloat16* bl = g_wl + (size_t)(n0 + row) * INDIM + kb + s_c16 * 8;
            CP_ASYNC16(base + XR_AH + so, ah);
            CP_ASYNC16(base + XR_AL + so, al);
            CP_ASYNC16(base + XR_BH + so, bh);
            CP_ASYNC16(base + XR_BL + so, bl);
        }
        CP_COMMIT();
    };

    stage(0, 0);

#pragma unroll 1
    for (int c = 0; c < 16; c++) {
        CP_WAIT0();
        __syncthreads();
        if (c < 15) stage(c + 1, (c + 1) & 1);

        const uint32_t base = sb + (c & 1) * XR_BUF;
#pragma unroll
        for (int kk = 0; kk < 4; kk++) {
            uint32_t ahf[2][4], alf[2][4];
#pragma unroll
            for (int mf = 0; mf < 2; mf++) {
                int r = wm * 32 + mf * 16 + a_ml;
                uint32_t co = (uint32_t)((((kk * 2 + a_kh) ^ (r & 7)) * 16) + r * 128);
                ldmx4(ahf[mf][0], ahf[mf][1], ahf[mf][2], ahf[mf][3], base + XR_AH + co);
                ldmx4(alf[mf][0], alf[mf][1], alf[mf][2], alf[mf][3], base + XR_AL + co);
            }
#pragma unroll
            for (int np = 0; np < 4; np++) {
                int r = wn * 64 + np * 16 + b_nl;
                uint32_t co = (uint32_t)((((kk * 2 + b_kh) ^ (r & 7)) * 16) + r * 128);
                uint32_t bh[4], bl[4];
                ldmx4(bh[0], bh[1], bh[2], bh[3], base + XR_BH + co);
                ldmx4(bl[0], bl[1], bl[2], bl[3], base + XR_BL + co);
#pragma unroll
                for (int mf = 0; mf < 2; mf++) {
                    mma16816(acc[mf][np * 2 + 0], ahf[mf], &bh[0]);
                    mma16816(acc[mf][np * 2 + 1], ahf[mf], &bh[2]);
                    mma16816(acc[mf][np * 2 + 0], ahf[mf], &bl[0]);
                    mma16816(acc[mf][np * 2 + 1], ahf[mf], &bl[2]);
                    mma16816(acc[mf][np * 2 + 0], alf[mf], &bh[0]);
                    mma16816(acc[mf][np * 2 + 1], alf[mf], &bh[2]);
                }
            }
        }
        __syncthreads();
    }

    const int lr = lid >> 2;
    const int lc = (lid & 3) * 2;
#pragma unroll
    for (int mf = 0; mf < 2; mf++) {
#pragma unroll
        for (int nf = 0; nf < 8; nf++) {
            int m = m0 + wm * 32 + mf * 16 + lr;
            int n = n0 + wn * 64 + nf * 8 + lc;
            float2 bv = __ldg((const float2*)(g_bias + n));
            float2 o0 = make_float2(acc[mf][nf][0] + bv.x, acc[mf][nf][1] + bv.y);
            float2 o1 = make_float2(acc[mf][nf][2] + bv.x, acc[mf][nf][3] + bv.y);
            *reinterpret_cast<float2*>(g_xg + (size_t)m * G4 + n)       = o0;
            *reinterpret_cast<float2*>(g_xg + (size_t)(m + 8) * G4 + n) = o1;
        }
    }
}

// ---------------------------------------------------------------------------
// grid barrier (sense-reversing; thread0 arrival + spin) — R11 proven
// ---------------------------------------------------------------------------
__device__ __forceinline__ void grid_bar(unsigned int target) {
    __threadfence();
    __syncthreads();
    if (threadIdx.x == 0) {
        unsigned int a = atomicAdd(&g_count, 1u);
        if (a == NBLK - 1) {
            atomicExch(&g_count, 0u);
            __threadfence();
            atomicExch(&g_sense, target);
        } else {
            volatile unsigned int* s = &g_sense;
            while (*s < target) { }
            __threadfence();
        }
    }
    __syncthreads();
}

// ---------------------------------------------------------------------------
// Tensorized persistent LSTM scan: 16 warps, wm4 (m16) x wn2 (n16) x ks2 (k512).
//   R11 pipeline + hard grid barrier; symmetric epilogue: warp (wm,wn,ks)
//   owns output rows rr==ks — gate math / xg prefetch / h stores spread
//   across all 16 warps via a symmetric split-K smem swap.
// ---------------------------------------------------------------------------
__global__ __launch_bounds__(SCAN_THR, 1) void lstm_scan(float* __restrict__ out) {
    extern __shared__ char smem[];
    const uint32_t sb = smem_to_u32(smem);
    const int tid = threadIdx.x;
    const int lid = tid & 31;
    const int wid = tid >> 5;          // 0..15
    const int wm  = wid & 3;           // m16 group (batch rows wm*16..+15)
    const int wn  = (wid >> 2) & 1;    // n16 group
    const int ks  = wid >> 3;          // k512 half; also owned row-half rr
    const int hbar = 1 + ks;           // named barrier id for this half
    const int jt  = blockIdx.x;
    const int j0  = jt * 32;

    const int a_ml = lid & 15;
    const int a_kh = (lid >> 4) & 1;
    const int b_nl = (lid & 7) + ((lid & 16) ? 8 : 0);
    const int b_kh = (lid >> 3) & 1;
    const int lc   = (lid & 3) * 2;
    const int lr   = lid >> 2;
    const int pa   = a_ml & 7;
    const int pb   = b_nl & 7;

    // --- persistent W_hh slice preload: [32 cols][2048 B] hi/lo, swizzled ---
#pragma unroll 4
    for (int i = 0; i < 8; i++) {
        int g = tid + 512 * i;            // 0..4095
        int row = g >> 7;                 // 0..31
        int slot = g & 127;
        uint4 vh = *(const uint4*)(g_uh + (size_t)(j0 + row) * HID + slot * 8);
        uint4 vl = *(const uint4*)(g_ul + (size_t)(j0 + row) * HID + slot * 8);
        uint32_t doff = (uint32_t)(row * 2048 + (slot >> 3) * 128 +
                                   (((slot & 7) ^ (row & 7)) * 16));
        *(uint4*)(smem + WSH_OFF + doff) = vh;
        *(uint4*)(smem + WSL_OFF + doff) = vl;
    }
    __syncthreads();

    // h chunk staging: task = (row b, k-half); 4 threads per task, 2 slots each.
    const int st_task = tid >> 2;        // 0..127
    const int st_b = st_task & 63;
    const int st_h = st_task >> 6;       // k-half (== ks for every thread)
    const int st_s = (tid & 3) * 2;

    // fragment bases
    const int a_row = wm * 16 + a_ml;
    const int b_row = wn * 16 + b_nl;
    const uint32_t bhb = sb + WSH_OFF + (uint32_t)(b_row * 2048);
    const uint32_t blb = sb + WSL_OFF + (uint32_t)(b_row * 2048);

    // epilogue geometry: this warp owns batch row b_own (+ its hj cols)
    const int b_own = wm * 16 + lr + ks * 8;
    const int tile  = wm * 2 + wn;       // 0..7

    float c_[2] = {0.f, 0.f};

#pragma unroll 1
    for (int t = 0; t < T_STEPS; t++) {
        const int cur = t & 1, nxt = cur ^ 1;
        const __nv_bfloat16* hhs = g_hh[cur];
        const __nv_bfloat16* hls = g_hl[cur];

        // xg prefetch for the rows this warp owns (hidden under k-loop)
        float2 xv[2];
#pragma unroll
        for (int nt = 0; nt < 2; nt++) {
            int col = j0 + wn * 16 + nt * 8 + lc;
            xv[nt] = *(const float2*)(g_xg + (size_t)t * (BATCH * G4) +
                                      (size_t)b_own * G4 + col);
        }

        float acc[2][4];
#pragma unroll
        for (int nt = 0; nt < 2; nt++)
#pragma unroll
            for (int q = 0; q < 4; q++) acc[nt][q] = 0.f;

        // stage chunk 0: (64 rows x 64k) for this half, hi+lo
        {
            const __nv_bfloat16* sH = hhs + st_b * HID + st_h * 512;
            const __nv_bfloat16* sL = hls + st_b * HID + st_h * 512;
            uint32_t dst = sb + HB_OFF + (uint32_t)(st_h * 16384 + st_b * 128);
#pragma unroll
            for (int j = 0; j < 2; j++) {
                int s = st_s + j;
                uint32_t doff = (uint32_t)((s ^ (st_b & 7)) * 16);
                CP_ASYNC16(dst + doff,        sH + s * 8);
                CP_ASYNC16(dst + 8192 + doff, sL + s * 8);
            }
            CP_COMMIT();
        }

        int buf = 0;
#pragma unroll 1
        for (int c = 0; c < 8; c++) {
            CP_WAIT0();
            BAR_SYNC(hbar, 256);        // per-half: staging visible to this half
            if (c < 7) {
                const __nv_bfloat16* sH = hhs + st_b * HID + st_h * 512 + (c + 1) * 64;
                const __nv_bfloat16* sL = hls + st_b * HID + st_h * 512 + (c + 1) * 64;
                uint32_t dst = sb + HB_OFF +
                               (uint32_t)((buf ^ 1) * 32768 + st_h * 16384 + st_b * 128);
#pragma unroll
                for (int j = 0; j < 2; j++) {
                    int s = st_s + j;
                    uint32_t doff = (uint32_t)((s ^ (st_b & 7)) * 16);
                    CP_ASYNC16(dst + doff,        sH + s * 8);
                    CP_ASYNC16(dst + 8192 + doff, sL + s * 8);
                }
                CP_COMMIT();
            }

            const uint32_t hbase = sb + HB_OFF + (uint32_t)(buf * 32768 + ks * 16384);
#pragma unroll
            for (int kk = 0; kk < 4; kk++) {
                uint32_t aoff = (uint32_t)(a_row * 128 + (((kk * 2 + a_kh) ^ pa) * 16));
                uint32_t ahf[4], alf[4];
                ldmx4(ahf[0], ahf[1], ahf[2], ahf[3], hbase + aoff);
                ldmx4(alf[0], alf[1], alf[2], alf[3], hbase + 8192 + aoff);
                int slot = ks * 64 + c * 8 + kk * 2 + b_kh;
                uint32_t boff = (uint32_t)((slot >> 3) * 128 + (((slot & 7) ^ pb) * 16));
                uint32_t bh[4], bl[4];
                ldmx4(bh[0], bh[1], bh[2], bh[3], bhb + boff);
                ldmx4(bl[0], bl[1], bl[2], bl[3], blb + boff);
                mma16816(acc[0], ahf, &bh[0]);
                mma16816(acc[1], ahf, &bh[2]);
                mma16816(acc[0], ahf, &bl[0]);
                mma16816(acc[1], ahf, &bl[2]);
                mma16816(acc[0], alf, &bh[0]);
                mma16816(acc[1], alf, &bh[2]);
            }
            buf ^= 1;
        }

        // ---- symmetric split-K exchange: send non-owned row-half, recv own ----
        {
            char* wrp = smem + RED_OFF + (tile * 2 + (1 - ks)) * 512 + lid * 16;
            *reinterpret_cast<float4*>(wrp) =
                make_float4(acc[0][(1 - ks) * 2], acc[0][(1 - ks) * 2 + 1],
                            acc[1][(1 - ks) * 2], acc[1][(1 - ks) * 2 + 1]);
        }
        __syncthreads();
        float gsum[2][2];
        {
            const char* rrp = smem + RED_OFF + (tile * 2 + ks) * 512 + lid * 16;
            float4 r = *reinterpret_cast<const float4*>(rrp);
            gsum[0][0] = acc[0][ks * 2]     + r.x;
            gsum[0][1] = acc[0][ks * 2 + 1] + r.y;
            gsum[1][0] = acc[1][ks * 2]     + r.z;
            gsum[1][1] = acc[1][ks * 2 + 1] + r.w;
        }

        // gates for owned rows: even lanes (i,f), odd lanes (g,o); shfl pair
#pragma unroll
        for (int nt = 0; nt < 2; nt++) {
            float g0 = gsum[nt][0] + xv[nt].x;
            float g1 = gsum[nt][1] + xv[nt].y;
            float p0 = __shfl_xor_sync(0xffffffffu, g0, 1);
            float p1 = __shfl_xor_sync(0xffffffffu, g1, 1);
            float gi = sigf(g0);
            float gf = sigf(g1);
            float gg = tanh_fast(p0);
            float go = sigf(p1);
            float cc2 = gf * c_[nt] + gi * gg;
            c_[nt] = cc2;
            float v = go * tanh_fast(cc2);
            if ((lid & 1) == 0) {
                int hjg = jt * 8 + wn * 4 + nt * 2 + (lc >> 2);
                __nv_bfloat16 hi = __float2bfloat16(v);
                __nv_bfloat16 lo = __float2bfloat16(v - __bfloat162float(hi));
                g_hh[nxt][b_own * HID + hjg] = hi;
                g_hl[nxt][b_own * HID + hjg] = lo;
                if (t == T_STEPS - 1) out[b_own * HID + hjg] = v;
            }
        }

        if (t != T_STEPS - 1) grid_bar((unsigned int)(t + 1));
    }
}

// ---------------------------------------------------------------------------
extern "C" void kernel_launch(void* const* d_in, const int* in_sizes, int n_in,
                              void* d_out, int out_size) {
    const float* x   = (const float*)d_in[0];
    const float* Wih = (const float*)d_in[1];
    const float* Whh = (const float*)d_in[2];
    const float* bih = (const float*)d_in[3];
    const float* bhh = (const float*)d_in[4];
    float* out = (float*)d_out;

    cudaFuncSetAttribute(xg_mma, cudaFuncAttributeMaxDynamicSharedMemorySize, XS_TOTAL);
    cudaFuncSetAttribute(lstm_scan, cudaFuncAttributeMaxDynamicSharedMemorySize, SCAN_SMEM);

    convert_inputs<<<CV_GRID, 256>>>(x, Wih, Whh, bih, bhh);
    xg_mma<<<dim3(G4 / MM_BN, (T_STEPS * BATCH) / MM_BM), MM_THR, XS_TOTAL>>>();
    lstm_scan<<<NBLK, SCAN_THR, SCAN_SMEM>>>(out);
}

// round 14
// speedup vs baseline: 1.1753x; 1.0965x over previous
#include <cuda_runtime.h>
#include <cuda_bf16.h>
#include <cstdint>

#define T_STEPS 512
#define BATCH   64
#define INDIM   1024
#define HID     1024
#define G4      4096

// scan config
#define NBLK     128
#define SCAN_THR 512
// scan smem layout (bytes)
#define WSH_OFF  0
#define WSL_OFF  65536
#define HB_OFF   131072
#define RED_OFF  196608
#define SCAN_SMEM 204800   // 128K W hi/lo + 2 x 32K h chunks + 8K reduction

// xg mma config (R5, proven)
#define MM_BM   128
#define MM_BN   128
#define MM_KC   64
#define MM_THR  256

// ---------------------------------------------------------------------------
// Global scratch
// ---------------------------------------------------------------------------
__device__ float g_xg[(size_t)T_STEPS * BATCH * G4];   // [m][j'] permuted, bias included
__device__ __nv_bfloat16 g_hh[2][BATCH * HID];         // h hi, [b][hj], double buffered
__device__ __nv_bfloat16 g_hl[2][BATCH * HID];         // h lo
__device__ __nv_bfloat16 g_xh[(size_t)T_STEPS * BATCH * INDIM];
__device__ __nv_bfloat16 g_xl[(size_t)T_STEPS * BATCH * INDIM];
__device__ __nv_bfloat16 g_wh[(size_t)G4 * INDIM];     // W_ih permuted rows, bf16 hi
__device__ __nv_bfloat16 g_wl[(size_t)G4 * INDIM];     // W_ih bf16 lo
__device__ __nv_bfloat16 g_uh[(size_t)G4 * HID];       // W_hh permuted rows, bf16 hi
__device__ __nv_bfloat16 g_ul[(size_t)G4 * HID];       // W_hh bf16 lo
__device__ float g_bias[G4];
__device__ unsigned int g_count;
__device__ unsigned int g_sense;

// ---------------------------------------------------------------------------
// Ampere-ISA helpers (plain compute_103)
// ---------------------------------------------------------------------------
__device__ __forceinline__ uint32_t smem_to_u32(const void* p) {
    uint32_t a;
    asm("{ .reg .u64 t; cvta.to.shared.u64 t, %1; cvt.u32.u64 %0, t; }" : "=r"(a) : "l"(p));
    return a;
}
__device__ __forceinline__ void ldmx4(uint32_t& r0, uint32_t& r1, uint32_t& r2,
                                      uint32_t& r3, uint32_t a) {
    asm volatile("ldmatrix.sync.aligned.m8n8.x4.shared.b16 {%0,%1,%2,%3}, [%4];"
                 : "=r"(r0), "=r"(r1), "=r"(r2), "=r"(r3) : "r"(a));
}
__device__ __forceinline__ void mma16816(float* d, const uint32_t* a, const uint32_t* b) {
    asm volatile(
        "mma.sync.aligned.m16n8k16.row.col.f32.bf16.bf16.f32 "
        "{%0,%1,%2,%3},{%4,%5,%6,%7},{%8,%9},{%0,%1,%2,%3};"
        : "+f"(d[0]), "+f"(d[1]), "+f"(d[2]), "+f"(d[3])
        : "r"(a[0]), "r"(a[1]), "r"(a[2]), "r"(a[3]), "r"(b[0]), "r"(b[1]));
}
#define CP_ASYNC16(s, g) \
    asm volatile("cp.async.cg.shared.global [%0], [%1], 16;" :: "r"(s), "l"(g) : "memory")
#define CP_COMMIT()  asm volatile("cp.async.commit_group;" ::: "memory")
#define CP_WAIT0()   asm volatile("cp.async.wait_group 0;" ::: "memory")
#define BAR_SYNC(id, n) \
    asm volatile("bar.sync %0, %1;" :: "r"(id), "r"(n) : "memory")

__device__ __forceinline__ float sigf(float x) {
    return __fdividef(1.0f, 1.0f + __expf(-x));
}
__device__ __forceinline__ float tanh_fast(float x) {
    return __fdividef(2.0f, 1.0f + __expf(-2.0f * x)) - 1.0f;
}

// ---------------------------------------------------------------------------
// Conversion: bf16 hi/lo of x, permuted W_ih AND permuted W_hh; bias; resets
// ---------------------------------------------------------------------------
#define CV_XU 8388608u
#define CV_WU 1048576u
#define CV_UU 1048576u
#define CV_BU 1024u
#define CV_HU 16384u
#define CV_GRID 41028u

__global__ void convert_inputs(const float* __restrict__ x,
                               const float* __restrict__ Wih,
                               const float* __restrict__ Whh,
                               const float* __restrict__ bih,
                               const float* __restrict__ bhh) {
    unsigned u = blockIdx.x * 256u + threadIdx.x;
    if (u < CV_XU) {
        float4 v = __ldg((const float4*)x + u);
        __nv_bfloat162 h01 = __floats2bfloat162_rn(v.x, v.y);
        __nv_bfloat162 h23 = __floats2bfloat162_rn(v.z, v.w);
        __nv_bfloat162 l01 = __floats2bfloat162_rn(v.x - __bfloat162float(h01.x),
                                                   v.y - __bfloat162float(h01.y));
        __nv_bfloat162 l23 = __floats2bfloat162_rn(v.z - __bfloat162float(h23.x),
                                                   v.w - __bfloat162float(h23.y));
        *(__nv_bfloat162*)(g_xh + (size_t)u * 4)     = h01;
        *(__nv_bfloat162*)(g_xh + (size_t)u * 4 + 2) = h23;
        *(__nv_bfloat162*)(g_xl + (size_t)u * 4)     = l01;
        *(__nv_bfloat162*)(g_xl + (size_t)u * 4 + 2) = l23;
    } else if (u < CV_XU + CV_WU) {
        unsigned uw = u - CV_XU;
        int np = uw >> 8;
        int kq = uw & 255;
        int jo = (np & 3) * HID + (np >> 2);
        float4 v = __ldg((const float4*)(Wih + (size_t)jo * INDIM) + kq);
        __nv_bfloat162 h01 = __floats2bfloat162_rn(v.x, v.y);
        __nv_bfloat162 h23 = __floats2bfloat162_rn(v.z, v.w);
        __nv_bfloat162 l01 = __floats2bfloat162_rn(v.x - __bfloat162float(h01.x),
                                                   v.y - __bfloat162float(h01.y));
        __nv_bfloat162 l23 = __floats2bfloat162_rn(v.z - __bfloat162float(h23.x),
                                                   v.w - __bfloat162float(h23.y));
        size_t base = (size_t)np * INDIM + kq * 4;
        *(__nv_bfloat162*)(g_wh + base)     = h01;
        *(__nv_bfloat162*)(g_wh + base + 2) = h23;
        *(__nv_bfloat162*)(g_wl + base)     = l01;
        *(__nv_bfloat162*)(g_wl + base + 2) = l23;
    } else if (u < CV_XU + CV_WU + CV_UU) {
        unsigned uw = u - CV_XU - CV_WU;
        int np = uw >> 8;
        int kq = uw & 255;
        int jo = (np & 3) * HID + (np >> 2);
        float4 v = __ldg((const float4*)(Whh + (size_t)jo * HID) + kq);
        __nv_bfloat162 h01 = __floats2bfloat162_rn(v.x, v.y);
        __nv_bfloat162 h23 = __floats2bfloat162_rn(v.z, v.w);
        __nv_bfloat162 l01 = __floats2bfloat162_rn(v.x - __bfloat162float(h01.x),
                                                   v.y - __bfloat162float(h01.y));
        __nv_bfloat162 l23 = __floats2bfloat162_rn(v.z - __bfloat162float(h23.x),
                                                   v.w - __bfloat162float(h23.y));
        size_t base = (size_t)np * HID + kq * 4;
        *(__nv_bfloat162*)(g_uh + base)     = h01;
        *(__nv_bfloat162*)(g_uh + base + 2) = h23;
        *(__nv_bfloat162*)(g_ul + base)     = l01;
        *(__nv_bfloat162*)(g_ul + base + 2) = l23;
    } else if (u < CV_XU + CV_WU + CV_UU + CV_BU) {
        unsigned ub = u - CV_XU - CV_WU - CV_UU;
        if (ub == 0) { g_count = 0u; g_sense = 0u; }
#pragma unroll
        for (int c = 0; c < 4; c++) {
            int np = ub * 4 + c;
            int jo = (np & 3) * HID + (np >> 2);
            g_bias[np] = bih[jo] + bhh[jo];
        }
    } else if (u < CV_XU + CV_WU + CV_UU + CV_BU + CV_HU) {
        unsigned uh = u - CV_XU - CV_WU - CV_UU - CV_BU;   // 0..16383
        if (uh < 8192u)
            reinterpret_cast<uint4*>(&g_hh[0][0])[uh] = make_uint4(0, 0, 0, 0);
        else
            reinterpret_cast<uint4*>(&g_hl[0][0])[uh - 8192u] = make_uint4(0, 0, 0, 0);
    }
}

// ---------------------------------------------------------------------------
// xg via mma.sync bf16 (3-term split) — R5, proven (unchanged)
// ---------------------------------------------------------------------------
#define XR_AH 0
#define XR_AL 16384
#define XR_BH 32768
#define XR_BL 49152
#define XR_BUF 65536
#define XS_TOTAL (2 * XR_BUF)

__global__ __launch_bounds__(MM_THR, 1) void xg_mma() {
    extern __shared__ char smem[];
    const uint32_t sb = smem_to_u32(smem);
    const int tid = threadIdx.x;
    const int lid = tid & 31;
    const int wid = tid >> 5;
    const int wm  = wid & 3;
    const int wn  = wid >> 2;
    const int n0  = blockIdx.x * MM_BN;
    const int m0  = blockIdx.y * MM_BM;

    const int s_row = tid >> 3;
    const int s_c16 = tid & 7;
    const int a_ml = lid & 15;
    const int a_kh = (lid >> 4) & 1;
    const int b_nl = (lid & 7) + ((lid & 16) ? 8 : 0);
    const int b_kh = (lid >> 3) & 1;

    float acc[2][8][4];
#pragma unroll
    for (int i = 0; i < 2; i++)
#pragma unroll
        for (int j = 0; j < 8; j++)
#pragma unroll
            for (int q = 0; q < 4; q++) acc[i][j][q] = 0.f;

    auto stage = [&](int c, int buf) {
        const int kb = c * MM_KC;
        const uint32_t base = sb + buf * XR_BUF;
#pragma unroll
        for (int p = 0; p < 4; p++) {
            int row = s_row + p * 32;
            uint32_t so = (uint32_t)(row * 128 + ((s_c16 ^ (row & 7)) * 16));
            const __nv_bfloat16* ah = g_xh + (size_t)(m0 + row) * INDIM + kb + s_c16 * 8;
            const __nv_bfloat16* al = g_xl + (size_t)(m0 + row) * INDIM + kb + s_c16 * 8;
            const __nv_bfloat16* bh = g_wh + (size_t)(n0 + row) * INDIM + kb + s_c16 * 8;
            const __nv_bfloat16* bl = g_wl + (size_t)(n0 + row) * INDIM + kb + s_c16 * 8;
            CP_ASYNC16(base + XR_AH + so, ah);
            CP_ASYNC16(base + XR_AL + so, al);
            CP_ASYNC16(base + XR_BH + so, bh);
            CP_ASYNC16(base + XR_BL + so, bl);
        }
        CP_COMMIT();
    };

    stage(0, 0);

#pragma unroll 1
    for (int c = 0; c < 16; c++) {
        CP_WAIT0();
        __syncthreads();
        if (c < 15) stage(c + 1, (c + 1) & 1);

        const uint32_t base = sb + (c & 1) * XR_BUF;
#pragma unroll
        for (int kk = 0; kk < 4; kk++) {
            uint32_t ahf[2][4], alf[2][4];
#pragma unroll
            for (int mf = 0; mf < 2; mf++) {
                int r = wm * 32 + mf * 16 + a_ml;
                uint32_t co = (uint32_t)((((kk * 2 + a_kh) ^ (r & 7)) * 16) + r * 128);
                ldmx4(ahf[mf][0], ahf[mf][1], ahf[mf][2], ahf[mf][3], base + XR_AH + co);
                ldmx4(alf[mf][0], alf[mf][1], alf[mf][2], alf[mf][3], base + XR_AL + co);
            }
#pragma unroll
            for (int np = 0; np < 4; np++) {
                int r = wn * 64 + np * 16 + b_nl;
                uint32_t co = (uint32_t)((((kk * 2 + b_kh) ^ (r & 7)) * 16) + r * 128);
                uint32_t bh[4], bl[4];
                ldmx4(bh[0], bh[1], bh[2], bh[3], base + XR_BH + co);
                ldmx4(bl[0], bl[1], bl[2], bl[3], base + XR_BL + co);
#pragma unroll
                for (int mf = 0; mf < 2; mf++) {
                    mma16816(acc[mf][np * 2 + 0], ahf[mf], &bh[0]);
                    mma16816(acc[mf][np * 2 + 1], ahf[mf], &bh[2]);
                    mma16816(acc[mf][np * 2 + 0], ahf[mf], &bl[0]);
                    mma16816(acc[mf][np * 2 + 1], ahf[mf], &bl[2]);
                    mma16816(acc[mf][np * 2 + 0], alf[mf], &bh[0]);
                    mma16816(acc[mf][np * 2 + 1], alf[mf], &bh[2]);
                }
            }
        }
        __syncthreads();
    }

    const int lr = lid >> 2;
    const int lc = (lid & 3) * 2;
#pragma unroll
    for (int mf = 0; mf < 2; mf++) {
#pragma unroll
        for (int nf = 0; nf < 8; nf++) {
            int m = m0 + wm * 32 + mf * 16 + lr;
            int n = n0 + wn * 64 + nf * 8 + lc;
            float2 bv = __ldg((const float2*)(g_bias + n));
            float2 o0 = make_float2(acc[mf][nf][0] + bv.x, acc[mf][nf][1] + bv.y);
            float2 o1 = make_float2(acc[mf][nf][2] + bv.x, acc[mf][nf][3] + bv.y);
            *reinterpret_cast<float2*>(g_xg + (size_t)m * G4 + n)       = o0;
            *reinterpret_cast<float2*>(g_xg + (size_t)(m + 8) * G4 + n) = o1;
        }
    }
}

// ---------------------------------------------------------------------------
// grid barrier (sense-reversing) with release/acquire semantics:
//   bar.sync gives intra-CTA happens-before; a single release-scoped arrival
//   by thread 0 then orders ALL the CTA's prior h-stores grid-wide. Removes
//   the per-step 512-thread MEMBAR.GPU of the previous version.
// ---------------------------------------------------------------------------
__device__ __forceinline__ void grid_bar(unsigned int target) {
    __syncthreads();
    if (threadIdx.x == 0) {
        unsigned int a;
        asm volatile("atom.add.release.gpu.global.u32 %0, [%1], 1;"
                     : "=r"(a) : "l"(&g_count) : "memory");
        if (a == NBLK - 1) {
            atomicExch(&g_count, 0u);   // reset, ordered before release below
            asm volatile("st.release.gpu.global.u32 [%0], %1;"
                         :: "l"(&g_sense), "r"(target) : "memory");
        } else {
            unsigned int s;
            do {
                asm volatile("ld.acquire.gpu.global.u32 %0, [%1];"
                             : "=r"(s) : "l"(&g_sense) : "memory");
            } while (s < target);
        }
    }
    __syncthreads();
}

// ---------------------------------------------------------------------------
// Tensorized persistent LSTM scan (R11 build, unchanged except grid_bar):
//   16 warps, wm4 (m16) x wn2 (n16) x ks2 (k512); per-half named barriers;
//   dedicated reduction region; asymmetric epilogue (ks0 warps do gates).
// ---------------------------------------------------------------------------
__global__ __launch_bounds__(SCAN_THR, 1) void lstm_scan(float* __restrict__ out) {
    extern __shared__ char smem[];
    const uint32_t sb = smem_to_u32(smem);
    const int tid = threadIdx.x;
    const int lid = tid & 31;
    const int wid = tid >> 5;          // 0..15
    const int wm  = wid & 3;           // m16 group (batch rows wm*16..+15)
    const int wn  = (wid >> 2) & 1;    // n16 group
    const int ks  = wid >> 3;          // k512 half
    const int hbar = 1 + ks;           // named barrier id for this half
    const int jt  = blockIdx.x;
    const int j0  = jt * 32;

    const int a_ml = lid & 15;
    const int a_kh = (lid >> 4) & 1;
    const int b_nl = (lid & 7) + ((lid & 16) ? 8 : 0);
    const int b_kh = (lid >> 3) & 1;
    const int lc   = (lid & 3) * 2;
    const int lr   = lid >> 2;
    const int pa   = a_ml & 7;
    const int pb   = b_nl & 7;

    // --- persistent W_hh slice preload: [32 cols][2048 B] hi/lo, swizzled ---
#pragma unroll 4
    for (int i = 0; i < 8; i++) {
        int g = tid + 512 * i;            // 0..4095
        int row = g >> 7;                 // 0..31
        int slot = g & 127;
        uint4 vh = *(const uint4*)(g_uh + (size_t)(j0 + row) * HID + slot * 8);
        uint4 vl = *(const uint4*)(g_ul + (size_t)(j0 + row) * HID + slot * 8);
        uint32_t doff = (uint32_t)(row * 2048 + (slot >> 3) * 128 +
                                   (((slot & 7) ^ (row & 7)) * 16));
        *(uint4*)(smem + WSH_OFF + doff) = vh;
        *(uint4*)(smem + WSL_OFF + doff) = vl;
    }
    __syncthreads();

    // h chunk staging: task = (row b, k-half); 4 threads per task, 2 slots each.
    const int st_task = tid >> 2;        // 0..127
    const int st_b = st_task & 63;
    const int st_h = st_task >> 6;       // k-half (== ks for every thread)
    const int st_s = (tid & 3) * 2;

    // fragment bases
    const int a_row = wm * 16 + a_ml;
    const int b_row = wn * 16 + b_nl;
    const uint32_t bhb = sb + WSH_OFF + (uint32_t)(b_row * 2048);
    const uint32_t blb = sb + WSL_OFF + (uint32_t)(b_row * 2048);

    float c_[4] = {0.f, 0.f, 0.f, 0.f};

#pragma unroll 1
    for (int t = 0; t < T_STEPS; t++) {
        const int cur = t & 1, nxt = cur ^ 1;
        const __nv_bfloat16* hhs = g_hh[cur];
        const __nv_bfloat16* hls = g_hl[cur];

        // xg prefetch (ks0 warps; hidden under k-loop)
        float2 xv[2][2];
        if (ks == 0) {
            const float* xgt = g_xg + (size_t)t * (BATCH * G4);
#pragma unroll
            for (int nt = 0; nt < 2; nt++)
#pragma unroll
                for (int rr = 0; rr < 2; rr++) {
                    int b = wm * 16 + lr + rr * 8;
                    int col = j0 + wn * 16 + nt * 8 + lc;
                    xv[nt][rr] = *(const float2*)(xgt + (size_t)b * G4 + col);
                }
        }

        float acc[2][4];
#pragma unroll
        for (int nt = 0; nt < 2; nt++)
#pragma unroll
            for (int q = 0; q < 4; q++) acc[nt][q] = 0.f;

        // stage chunk 0: (64 rows x 64k) for this half, hi+lo
        {
            const __nv_bfloat16* sH = hhs + st_b * HID + st_h * 512;
            const __nv_bfloat16* sL = hls + st_b * HID + st_h * 512;
            uint32_t dst = sb + HB_OFF + (uint32_t)(st_h * 16384 + st_b * 128);
#pragma unroll
            for (int j = 0; j < 2; j++) {
                int s = st_s + j;
                uint32_t doff = (uint32_t)((s ^ (st_b & 7)) * 16);
                CP_ASYNC16(dst + doff,        sH + s * 8);
                CP_ASYNC16(dst + 8192 + doff, sL + s * 8);
            }
            CP_COMMIT();
        }

        int buf = 0;
#pragma unroll 1
        for (int c = 0; c < 8; c++) {
            CP_WAIT0();
            BAR_SYNC(hbar, 256);        // per-half: staging visible to this half
            if (c < 7) {
                const __nv_bfloat16* sH = hhs + st_b * HID + st_h * 512 + (c + 1) * 64;
                const __nv_bfloat16* sL = hls + st_b * HID + st_h * 512 + (c + 1) * 64;
                uint32_t dst = sb + HB_OFF +
                               (uint32_t)((buf ^ 1) * 32768 + st_h * 16384 + st_b * 128);
#pragma unroll
                for (int j = 0; j < 2; j++) {
                    int s = st_s + j;
                    uint32_t doff = (uint32_t)((s ^ (st_b & 7)) * 16);
                    CP_ASYNC16(dst + doff,        sH + s * 8);
                    CP_ASYNC16(dst + 8192 + doff, sL + s * 8);
                }
                CP_COMMIT();
            }

            const uint32_t hbase = sb + HB_OFF + (uint32_t)(buf * 32768 + ks * 16384);
#pragma unroll
            for (int kk = 0; kk < 4; kk++) {
                uint32_t aoff = (uint32_t)(a_row * 128 + (((kk * 2 + a_kh) ^ pa) * 16));
                uint32_t ahf[4], alf[4];
                ldmx4(ahf[0], ahf[1], ahf[2], ahf[3], hbase + aoff);
                ldmx4(alf[0], alf[1], alf[2], alf[3], hbase + 8192 + aoff);
                int slot = ks * 64 + c * 8 + kk * 2 + b_kh;
                uint32_t boff = (uint32_t)((slot >> 3) * 128 + (((slot & 7) ^ pb) * 16));
                uint32_t bh[4], bl[4];
                ldmx4(bh[0], bh[1], bh[2], bh[3], bhb + boff);
                ldmx4(bl[0], bl[1], bl[2], bl[3], blb + boff);
                mma16816(acc[0], ahf, &bh[0]);
                mma16816(acc[1], ahf, &bh[2]);
                mma16816(acc[0], ahf, &bl[0]);
                mma16816(acc[1], ahf, &bl[2]);
                mma16816(acc[0], alf, &bh[0]);
                mma16816(acc[1], alf, &bh[2]);
            }
            buf ^= 1;
        }

        // ---- split-K(2) reduction: ks1 partials -> dedicated region ----
        if (ks == 1) {
            char* rp = smem + RED_OFF + (wid - 8) * 1024 + lid * 32;
            *reinterpret_cast<float4*>(rp)      =
                make_float4(acc[0][0], acc[0][1], acc[0][2], acc[0][3]);
            *reinterpret_cast<float4*>(rp + 16) =
                make_float4(acc[1][0], acc[1][1], acc[1][2], acc[1][3]);
        }
        __syncthreads();

        if (ks == 0) {
            const char* rp = smem + RED_OFF + wid * 1024 + lid * 32;
            float4 r0 = *reinterpret_cast<const float4*>(rp);
            float4 r1 = *reinterpret_cast<const float4*>(rp + 16);
            acc[0][0] += r0.x; acc[0][1] += r0.y; acc[0][2] += r0.z; acc[0][3] += r0.w;
            acc[1][0] += r1.x; acc[1][1] += r1.y; acc[1][2] += r1.z; acc[1][3] += r1.w;

            // gates: even lanes hold (i,f), odd lanes (g,o); exchange via shfl
#pragma unroll
            for (int nt = 0; nt < 2; nt++)
#pragma unroll
                for (int rr = 0; rr < 2; rr++) {
                    float g0 = acc[nt][rr * 2 + 0] + xv[nt][rr].x;
                    float g1 = acc[nt][rr * 2 + 1] + xv[nt][rr].y;
                    float p0 = __shfl_xor_sync(0xffffffffu, g0, 1);
                    float p1 = __shfl_xor_sync(0xffffffffu, g1, 1);
                    float gi = sigf(g0);
                    float gf = sigf(g1);
                    float gg = tanh_fast(p0);
                    float go = sigf(p1);
                    int ci = nt * 2 + rr;
                    float cc2 = gf * c_[ci] + gi * gg;
                    c_[ci] = cc2;
                    float v = go * tanh_fast(cc2);
                    if ((lid & 1) == 0) {
                        int b = wm * 16 + lr + rr * 8;
                        int hjg = jt * 8 + wn * 4 + nt * 2 + (lc >> 2);
                        __nv_bfloat16 hi = __float2bfloat16(v);
                        __nv_bfloat16 lo = __float2bfloat16(v - __bfloat162float(hi));
                        g_hh[nxt][b * HID + hjg] = hi;
                        g_hl[nxt][b * HID + hjg] = lo;
                        if (t == T_STEPS - 1) out[b * HID + hjg] = v;
                    }
                }
        }

        if (t != T_STEPS - 1) grid_bar((unsigned int)(t + 1));
    }
}

// ---------------------------------------------------------------------------
extern "C" void kernel_launch(void* const* d_in, const int* in_sizes, int n_in,
                              void* d_out, int out_size) {
    const float* x   = (const float*)d_in[0];
    const float* Wih = (const float*)d_in[1];
    const float* Whh = (const float*)d_in[2];
    const float* bih = (const float*)d_in[3];
    const float* bhh = (const float*)d_in[4];
    float* out = (float*)d_out;

    cudaFuncSetAttribute(xg_mma, cudaFuncAttributeMaxDynamicSharedMemorySize, XS_TOTAL);
    cudaFuncSetAttribute(lstm_scan, cudaFuncAttributeMaxDynamicSharedMemorySize, SCAN_SMEM);

    convert_inputs<<<CV_GRID, 256>>>(x, Wih, Whh, bih, bhh);
    xg_mma<<<dim3(G4 / MM_BN, (T_STEPS * BATCH) / MM_BM), MM_THR, XS_TOTAL>>>();
    lstm_scan<<<NBLK, SCAN_THR, SCAN_SMEM>>>(out);
}